// round 1
// baseline (speedup 1.0000x reference)
#include <cuda_runtime.h>
#include <math.h>

#define N_ROWS 131072
#define D      2048
#define NT     256          // threads per block
#define CPT    8            // columns per thread = D / NT
#define NBLK   1024         // main-kernel blocks
#define ROWS_PER_BLK (N_ROWS / NBLK)   // 128
#define RB     4            // rows processed per batch (MLP + barrier amortization)
#define INV_T  10.0f        // 1 / temperature
#define EPS    1e-8f

// Scratch (device globals: no allocations allowed in kernel_launch)
__device__ float g_pacc[(size_t)NBLK * D];   // per-block partial weighted sums (8 MB)
__device__ float g_pm[NBLK];                 // per-block running max logit
__device__ float g_pl[NBLK];                 // per-block running sum of exp
__device__ float g_scale[NBLK];              // final per-block combine scale

// ---------------------------------------------------------------------------
// Main single-pass kernel: flash-style online softmin + weighted accumulation.
// Each block owns ROWS_PER_BLK consecutive rows; each thread owns 8 columns
// (cols tid*8 .. tid*8+7, loaded as two float4 -> fully coalesced LDG.128).
// ---------------------------------------------------------------------------
__global__ __launch_bounds__(NT) void dsdm_main(const float* __restrict__ A,
                                                const float* __restrict__ q) {
    __shared__ float s_dot[8][RB];
    __shared__ float s_sq[8][RB];
    __shared__ float s_logit[RB];
    __shared__ float s_tmp[8];

    const int tid  = threadIdx.x;
    const int wid  = tid >> 5;
    const int lane = tid & 31;

    // --- load q slice and compute ||q|| (redundant per block; hits L2) ---
    float qv[CPT];
    {
        const float4 q0 = reinterpret_cast<const float4*>(q)[tid * 2 + 0];
        const float4 q1 = reinterpret_cast<const float4*>(q)[tid * 2 + 1];
        qv[0] = q0.x; qv[1] = q0.y; qv[2] = q0.z; qv[3] = q0.w;
        qv[4] = q1.x; qv[5] = q1.y; qv[6] = q1.z; qv[7] = q1.w;
    }
    float qsq = 0.f;
    #pragma unroll
    for (int i = 0; i < CPT; i++) qsq += qv[i] * qv[i];
    #pragma unroll
    for (int o = 16; o; o >>= 1) qsq += __shfl_xor_sync(0xffffffffu, qsq, o);
    if (lane == 0) s_tmp[wid] = qsq;
    __syncthreads();
    if (tid == 0) {
        float s = 0.f;
        #pragma unroll
        for (int w = 0; w < 8; w++) s += s_tmp[w];
        s_tmp[0] = sqrtf(s);
    }
    __syncthreads();
    const float qn = s_tmp[0];
    __syncthreads();   // protect s_tmp reuse boundary (none after, but cheap)

    // --- online softmax state ---
    float acc[CPT];
    #pragma unroll
    for (int i = 0; i < CPT; i++) acc[i] = 0.f;
    float m = -1e30f;
    float l = 0.f;

    const size_t base = (size_t)blockIdx.x * ROWS_PER_BLK * D;

    for (int b = 0; b < ROWS_PER_BLK; b += RB) {
        float rv[RB][CPT];
        float dt[RB], sq[RB];

        // Front-batched loads: RB*2 = 8 LDG.128 issued back-to-back per thread
        #pragma unroll
        for (int r = 0; r < RB; r++) {
            const float4* rp =
                reinterpret_cast<const float4*>(A + base + (size_t)(b + r) * D) + tid * 2;
            const float4 v0 = rp[0];
            const float4 v1 = rp[1];
            rv[r][0] = v0.x; rv[r][1] = v0.y; rv[r][2] = v0.z; rv[r][3] = v0.w;
            rv[r][4] = v1.x; rv[r][5] = v1.y; rv[r][6] = v1.z; rv[r][7] = v1.w;
            float d = 0.f, s = 0.f;
            #pragma unroll
            for (int i = 0; i < CPT; i++) {
                d += rv[r][i] * qv[i];
                s += rv[r][i] * rv[r][i];
            }
            dt[r] = d; sq[r] = s;
        }

        // Warp-level reduction of RB dot/sq pairs
        #pragma unroll
        for (int r = 0; r < RB; r++) {
            #pragma unroll
            for (int o = 16; o; o >>= 1) {
                dt[r] += __shfl_xor_sync(0xffffffffu, dt[r], o);
                sq[r] += __shfl_xor_sync(0xffffffffu, sq[r], o);
            }
        }
        if (lane == 0) {
            #pragma unroll
            for (int r = 0; r < RB; r++) { s_dot[wid][r] = dt[r]; s_sq[wid][r] = sq[r]; }
        }
        __syncthreads();

        // Threads 0..RB-1 finish cross-warp reduction and compute logits
        if (tid < RB) {
            float d = 0.f, s = 0.f;
            #pragma unroll
            for (int w = 0; w < 8; w++) { d += s_dot[w][tid]; s += s_sq[w][tid]; }
            const float sim = d / fmaxf(sqrtf(s) * qn, EPS);
            s_logit[tid] = sim * INV_T;   // constant shift of softmax cancels
        }
        __syncthreads();

        // Online update (ordered over the RB rows)
        #pragma unroll
        for (int r = 0; r < RB; r++) {
            const float lg = s_logit[r];
            const float mn = fmaxf(m, lg);
            const float cs = __expf(m - mn);
            const float w  = __expf(lg - mn);
            m = mn;
            l = l * cs + w;
            #pragma unroll
            for (int i = 0; i < CPT; i++) acc[i] = acc[i] * cs + w * rv[r][i];
        }
        // Next iteration's first smem write (s_dot) is a different buffer than
        // s_logit reads above, and its own __syncthreads() orders the s_logit
        // rewrite -> no extra barrier needed here.
    }

    // Write partials
    if (tid == 0) { g_pm[blockIdx.x] = m; g_pl[blockIdx.x] = l; }
    float4* pa = reinterpret_cast<float4*>(g_pacc + (size_t)blockIdx.x * D) + tid * 2;
    pa[0] = make_float4(acc[0], acc[1], acc[2], acc[3]);
    pa[1] = make_float4(acc[4], acc[5], acc[6], acc[7]);
}

// ---------------------------------------------------------------------------
// Finalize 1: global log-sum-exp merge -> per-block scales (single block)
// ---------------------------------------------------------------------------
__global__ __launch_bounds__(NT) void dsdm_scales() {
    __shared__ float s_red[NT];
    const int tid = threadIdx.x;

    float mloc = -1e30f;
    for (int b = tid; b < NBLK; b += NT) mloc = fmaxf(mloc, g_pm[b]);
    s_red[tid] = mloc;
    __syncthreads();
    for (int o = NT / 2; o; o >>= 1) {
        if (tid < o) s_red[tid] = fmaxf(s_red[tid], s_red[tid + o]);
        __syncthreads();
    }
    const float M = s_red[0];
    __syncthreads();

    float lloc = 0.f;
    for (int b = tid; b < NBLK; b += NT) lloc += __expf(g_pm[b] - M) * g_pl[b];
    s_red[tid] = lloc;
    __syncthreads();
    for (int o = NT / 2; o; o >>= 1) {
        if (tid < o) s_red[tid] += s_red[tid + o];
        __syncthreads();
    }
    const float L = s_red[0];
    __syncthreads();

    const float invL = 1.0f / L;
    for (int b = tid; b < NBLK; b += NT) g_scale[b] = __expf(g_pm[b] - M) * invL;
}

// ---------------------------------------------------------------------------
// Finalize 2: out[col] = sum_b scale[b] * pacc[b][col]   (8 blocks x 256 thr)
// ---------------------------------------------------------------------------
__global__ __launch_bounds__(NT) void dsdm_out(float* __restrict__ out) {
    const int col = blockIdx.x * NT + threadIdx.x;
    float s = 0.f;
    #pragma unroll 8
    for (int b = 0; b < NBLK; b++) {
        s += g_scale[b] * g_pacc[(size_t)b * D + col];
    }
    out[col] = s;
}

extern "C" void kernel_launch(void* const* d_in, const int* in_sizes, int n_in,
                              void* d_out, int out_size) {
    const float* addresses = (const float*)d_in[0];   // [131072, 2048] f32
    const float* query     = (const float*)d_in[1];   // [2048] f32
    float* out = (float*)d_out;                       // [2048] f32

    dsdm_main<<<NBLK, NT>>>(addresses, query);
    dsdm_scales<<<1, NT>>>();
    dsdm_out<<<D / NT, NT>>>(out);
}

// round 2
// speedup vs baseline: 1.7689x; 1.7689x over previous
#include <cuda_runtime.h>
#include <math.h>

#define N_ROWS 131072
#define D      2048
#define NT     256            // threads per block
#define CPT    8              // columns per thread = D / NT
#define NBLK   296            // persistent grid = 2 * 148 SMs
#define RB     4              // rows per batch
#define NBATCH (N_ROWS / RB)  // 32768
#define NBY    8              // b-chunks in finalize
#define BCH    (NBLK / NBY)   // 37 partials per finalize block
#define INV_T  10.0f          // 1 / temperature
#define EPS    1e-8f

// Scratch (device globals: no allocations allowed)
__device__ float g_pacc[(size_t)NBLK * D];   // per-block partial weighted sums
__device__ float g_pm[NBLK];
__device__ float g_pl[NBLK];
__device__ float g_scale[NBLK];

// ---------------------------------------------------------------------------
// Main persistent kernel: flash-style online softmin, double-buffered loads.
// Each thread owns 8 columns (two float4). Per batch of RB=4 rows a thread
// issues 8 LDG.128; the NEXT batch's loads are issued before the current
// batch's reduction/barriers so DRAM stays busy across the barrier phase.
// ---------------------------------------------------------------------------
__global__ __launch_bounds__(NT) void dsdm_main(const float* __restrict__ A,
                                                const float* __restrict__ q) {
    __shared__ float s_dot[8][RB];
    __shared__ float s_sq[8][RB];
    __shared__ float s_logit[RB];
    __shared__ float s_tmp[8];

    const int tid  = threadIdx.x;
    const int wid  = tid >> 5;
    const int lane = tid & 31;

    // --- q slice + ||q|| ---
    float qv[CPT];
    {
        const float4 q0 = reinterpret_cast<const float4*>(q)[tid * 2 + 0];
        const float4 q1 = reinterpret_cast<const float4*>(q)[tid * 2 + 1];
        qv[0] = q0.x; qv[1] = q0.y; qv[2] = q0.z; qv[3] = q0.w;
        qv[4] = q1.x; qv[5] = q1.y; qv[6] = q1.z; qv[7] = q1.w;
    }
    float qsq = 0.f;
    #pragma unroll
    for (int i = 0; i < CPT; i++) qsq += qv[i] * qv[i];
    #pragma unroll
    for (int o = 16; o; o >>= 1) qsq += __shfl_xor_sync(0xffffffffu, qsq, o);
    if (lane == 0) s_tmp[wid] = qsq;
    __syncthreads();
    if (tid == 0) {
        float s = 0.f;
        #pragma unroll
        for (int w = 0; w < 8; w++) s += s_tmp[w];
        s_tmp[0] = sqrtf(s);
    }
    __syncthreads();
    const float qn = s_tmp[0];
    __syncthreads();

    float acc[CPT];
    #pragma unroll
    for (int i = 0; i < CPT; i++) acc[i] = 0.f;
    float m = -1e30f;
    float l = 0.f;

    // double-buffered row registers: RB rows x 2 float4 each
    float4 bA0[RB], bA1[RB], bB0[RB], bB1[RB];

#define LOAD_BATCH(v0, v1, batch)                                             \
    {                                                                         \
        _Pragma("unroll")                                                     \
        for (int r = 0; r < RB; r++) {                                        \
            const float4* rp = reinterpret_cast<const float4*>(               \
                A + ((size_t)(batch) * RB + r) * D) + tid * 2;                \
            v0[r] = rp[0];                                                    \
            v1[r] = rp[1];                                                    \
        }                                                                     \
    }

#define PROCESS(v0, v1)                                                       \
    {                                                                         \
        float dt[RB], sq[RB];                                                 \
        _Pragma("unroll")                                                     \
        for (int r = 0; r < RB; r++) {                                        \
            float d = v0[r].x * qv[0] + v0[r].y * qv[1] +                     \
                      v0[r].z * qv[2] + v0[r].w * qv[3] +                     \
                      v1[r].x * qv[4] + v1[r].y * qv[5] +                     \
                      v1[r].z * qv[6] + v1[r].w * qv[7];                      \
            float s = v0[r].x * v0[r].x + v0[r].y * v0[r].y +                 \
                      v0[r].z * v0[r].z + v0[r].w * v0[r].w +                 \
                      v1[r].x * v1[r].x + v1[r].y * v1[r].y +                 \
                      v1[r].z * v1[r].z + v1[r].w * v1[r].w;                  \
            dt[r] = d; sq[r] = s;                                             \
        }                                                                     \
        _Pragma("unroll")                                                     \
        for (int r = 0; r < RB; r++) {                                        \
            _Pragma("unroll")                                                 \
            for (int o = 16; o; o >>= 1) {                                    \
                dt[r] += __shfl_xor_sync(0xffffffffu, dt[r], o);              \
                sq[r] += __shfl_xor_sync(0xffffffffu, sq[r], o);              \
            }                                                                 \
        }                                                                     \
        if (lane == 0) {                                                      \
            _Pragma("unroll")                                                 \
            for (int r = 0; r < RB; r++) {                                    \
                s_dot[wid][r] = dt[r]; s_sq[wid][r] = sq[r];                  \
            }                                                                 \
        }                                                                     \
        __syncthreads();                                                      \
        if (tid < RB) {                                                       \
            float d = 0.f, s = 0.f;                                           \
            _Pragma("unroll")                                                 \
            for (int w = 0; w < 8; w++) { d += s_dot[w][tid]; s += s_sq[w][tid]; } \
            s_logit[tid] = (d / fmaxf(sqrtf(s) * qn, EPS)) * INV_T;           \
        }                                                                     \
        __syncthreads();                                                      \
        _Pragma("unroll")                                                     \
        for (int r = 0; r < RB; r++) {                                        \
            const float lg = s_logit[r];                                      \
            const float mn = fmaxf(m, lg);                                    \
            const float cs = __expf(m - mn);                                  \
            const float w  = __expf(lg - mn);                                 \
            m = mn;                                                           \
            l = l * cs + w;                                                   \
            acc[0] = acc[0] * cs + w * v0[r].x;                               \
            acc[1] = acc[1] * cs + w * v0[r].y;                               \
            acc[2] = acc[2] * cs + w * v0[r].z;                               \
            acc[3] = acc[3] * cs + w * v0[r].w;                               \
            acc[4] = acc[4] * cs + w * v1[r].x;                               \
            acc[5] = acc[5] * cs + w * v1[r].y;                               \
            acc[6] = acc[6] * cs + w * v1[r].z;                               \
            acc[7] = acc[7] * cs + w * v1[r].w;                               \
        }                                                                     \
    }

    // --- grid-stride pipeline over batches, unrolled x2 for reg buffers ---
    int batch = blockIdx.x;
    bool valid = (batch < NBATCH);
    if (valid) LOAD_BATCH(bA0, bA1, batch);

    while (valid) {
        int nb = batch + NBLK;
        bool vnext = (nb < NBATCH);
        if (vnext) LOAD_BATCH(bB0, bB1, nb);   // prefetch flies over barriers
        PROCESS(bA0, bA1);
        batch = nb; valid = vnext;
        if (!valid) break;

        nb = batch + NBLK;
        vnext = (nb < NBATCH);
        if (vnext) LOAD_BATCH(bA0, bA1, nb);
        PROCESS(bB0, bB1);
        batch = nb; valid = vnext;
    }

    if (tid == 0) { g_pm[blockIdx.x] = m; g_pl[blockIdx.x] = l; }
    float4* pa = reinterpret_cast<float4*>(g_pacc + (size_t)blockIdx.x * D) + tid * 2;
    pa[0] = make_float4(acc[0], acc[1], acc[2], acc[3]);
    pa[1] = make_float4(acc[4], acc[5], acc[6], acc[7]);
#undef LOAD_BATCH
#undef PROCESS
}

// ---------------------------------------------------------------------------
// Zero the output (harness poisons it).
// ---------------------------------------------------------------------------
__global__ __launch_bounds__(NT) void dsdm_zero(float* __restrict__ out) {
    #pragma unroll
    for (int i = 0; i < D / NT; i++) out[threadIdx.x + i * NT] = 0.f;
}

// ---------------------------------------------------------------------------
// Global log-sum-exp merge -> per-block scales (single tiny block).
// ---------------------------------------------------------------------------
__global__ __launch_bounds__(NT) void dsdm_scales() {
    __shared__ float s_red[NT];
    const int tid = threadIdx.x;

    float mloc = -1e30f;
    for (int b = tid; b < NBLK; b += NT) mloc = fmaxf(mloc, g_pm[b]);
    s_red[tid] = mloc;
    __syncthreads();
    for (int o = NT / 2; o; o >>= 1) {
        if (tid < o) s_red[tid] = fmaxf(s_red[tid], s_red[tid + o]);
        __syncthreads();
    }
    const float M = s_red[0];
    __syncthreads();

    float lloc = 0.f;
    for (int b = tid; b < NBLK; b += NT) lloc += __expf(g_pm[b] - M) * g_pl[b];
    s_red[tid] = lloc;
    __syncthreads();
    for (int o = NT / 2; o; o >>= 1) {
        if (tid < o) s_red[tid] += s_red[tid + o];
        __syncthreads();
    }
    const float L = s_red[0];
    __syncthreads();

    const float invL = 1.0f / L;
    for (int b = tid; b < NBLK; b += NT) g_scale[b] = __expf(g_pm[b] - M) * invL;
}

// ---------------------------------------------------------------------------
// Parallel combine: grid (D/NT, NBY); each block sums BCH partials for its
// 256 columns (coalesced) and atomically adds into out.
// ---------------------------------------------------------------------------
__global__ __launch_bounds__(NT) void dsdm_out(float* __restrict__ out) {
    const int col = blockIdx.x * NT + threadIdx.x;
    const int b0  = blockIdx.y * BCH;
    float s = 0.f;
    #pragma unroll
    for (int j = 0; j < BCH; j++) {
        s += g_scale[b0 + j] * g_pacc[(size_t)(b0 + j) * D + col];
    }
    atomicAdd(&out[col], s);
}

extern "C" void kernel_launch(void* const* d_in, const int* in_sizes, int n_in,
                              void* d_out, int out_size) {
    const float* addresses = (const float*)d_in[0];   // [131072, 2048] f32
    const float* query     = (const float*)d_in[1];   // [2048] f32
    float* out = (float*)d_out;                       // [2048] f32

    dsdm_main<<<NBLK, NT>>>(addresses, query);
    dsdm_zero<<<1, NT>>>(out);
    dsdm_scales<<<1, NT>>>();
    dsdm_out<<<dim3(D / NT, NBY), NT>>>(out);
}